// round 7
// baseline (speedup 1.0000x reference)
#include <cuda_runtime.h>
#include <math_constants.h>

#define IMG_H 64
#define IMG_W 2048
#define KNN_CUTOFF 1.0f
#define P_CAP 131072

// inv_g[k] = 1 - gauss(k)/sum(gauss), sigma=1, 5x5, row-major (ky,kx)
__device__ __constant__ float INV_G_C[25] = {
    0.99703098f, 0.98669378f, 0.97806177f, 0.98669378f, 0.99703098f,
    0.98669378f, 0.94036569f, 0.90167956f, 0.94036569f, 0.98669378f,
    0.97806177f, 0.90167956f, 0.83789717f, 0.90167956f, 0.97806177f,
    0.98669378f, 0.94036569f, 0.90167956f, 0.94036569f, 0.98669378f,
    0.99703098f, 0.98669378f, 0.97806177f, 0.98669378f, 0.99703098f
};

// compile-time-foldable copy (immediates in FMUL, no LDC in hot path)
__device__ __forceinline__ constexpr float inv_g_k(int k) {
    constexpr float g[25] = {
        0.99703098f, 0.98669378f, 0.97806177f, 0.98669378f, 0.99703098f,
        0.98669378f, 0.94036569f, 0.90167956f, 0.94036569f, 0.98669378f,
        0.97806177f, 0.90167956f, 0.83789717f, 0.90167956f, 0.97806177f,
        0.98669378f, 0.94036569f, 0.90167956f, 0.94036569f, 0.98669378f,
        0.99703098f, 0.98669378f, 0.97806177f, 0.98669378f, 0.99703098f
    };
    return g[k];
}

// per point: (contribution mask << 32) | (y0*W + x0)
__device__ unsigned long long g_sel[P_CAP];

// ---------------------------------------------------------------------------
// Kernel A: cutoff-mask selection. 1 thread/point.
// Fast path: <=5 below cutoff  => mask is exactly the cutoff set.
// Rare path (>5 below cutoff, ~5e-4): exact top-5 with index tiebreak.
// ---------------------------------------------------------------------------
__global__ __launch_bounds__(256)
void knn_select(const float* __restrict__ proj_range,
                const float* __restrict__ unproj,
                const int*   __restrict__ px,
                const int*   __restrict__ py,
                int P)
{
    int p = blockIdx.x * blockDim.x + threadIdx.x;
    if (p >= P) return;

    const int x0 = px[p];
    const int y0 = py[p];
    const float ur = unproj[p];

    unsigned mask = 0;   // d <= cutoff (with r<0 -> inf excluded)
    unsigned ib   = 0;   // in-bounds bits

    if (x0 >= 2 && x0 <= IMG_W - 3) {
        // interior: whole window in-row; 2 aligned float4 loads per row
        const int xb   = x0 - 2;
        const int base = xb & ~3;          // aligned, in [0, W-8] since W%4==0
        const bool b1  = (xb & 2) != 0;
        const bool b0  = (xb & 1) != 0;
#pragma unroll
        for (int row = 0; row < 5; ++row) {
            const int yy  = y0 + row - 2;
            const bool rv = ((unsigned)yy < (unsigned)IMG_H);
            const int yyc = rv ? yy : 0;
            const float4* rp = (const float4*)(proj_range + yyc * IMG_W + base);
            const float4 lo = __ldg(rp);
            const float4 hi = __ldg(rp + 1);
            // select window f[xb&3 .. xb&3+4] out of 8 via 2-level tree (11 SELs)
            const float h0 = b1 ? lo.z : lo.x;
            const float h1 = b1 ? lo.w : lo.y;
            const float h2 = b1 ? hi.x : lo.z;
            const float h3 = b1 ? hi.y : lo.w;
            const float h4 = b1 ? hi.z : hi.x;
            const float h5 = b1 ? hi.w : hi.y;
            float wv[5];
            wv[0] = b0 ? h1 : h0;
            wv[1] = b0 ? h2 : h1;
            wv[2] = b0 ? h3 : h2;
            wv[3] = b0 ? h4 : h3;
            wv[4] = b0 ? h5 : h4;
#pragma unroll
            for (int i = 0; i < 5; ++i) {
                const int k = row * 5 + i;
                const float r = rv ? wv[i] : 0.0f;
                const float d = fabsf(r - ur) * inv_g_k(k);
                if ((d <= KNN_CUTOFF) && (r >= 0.0f)) mask |= (1u << k);
                if (rv)                                ib   |= (1u << k);
            }
        }
    } else {
        // edge columns (~0.25% of points): scalar loads
#pragma unroll
        for (int k = 0; k < 25; ++k) {
            const int yy = y0 + (k / 5) - 2;
            const int xx = x0 + (k % 5) - 2;
            const bool valid = ((unsigned)yy < (unsigned)IMG_H) &&
                               ((unsigned)xx < (unsigned)IMG_W);
            const float r = valid ? __ldg(proj_range + yy * IMG_W + xx) : 0.0f;
            const float d = fabsf(r - ur) * inv_g_k(k);
            if ((d <= KNN_CUTOFF) && (r >= 0.0f)) mask |= (1u << k);
            if (valid)                             ib   |= (1u << k);
        }
    }

    mask |= (1u << 12);   // center: d forced to 0, always passes (always in-bounds)
    ib   |= (1u << 12);

    if (__popc(mask) > 5) {
        // exact top-5 (ascending value, lowest index on ties); all 5 winners
        // necessarily have d <= cutoff since >5 elements are below cutoff.
        // Out-of-bounds (r=0) candidates legitimately compete for slots here.
        unsigned nm = 0;
        for (int s = 0; s < 5; ++s) {
            unsigned long long best = ~0ull;
            int bi = 0;
            for (int k = 0; k < 25; ++k) {
                if (nm & (1u << k)) continue;
                float d;
                if (k == 12) {
                    d = 0.0f;
                } else {
                    const int yy = y0 + (k / 5) - 2;
                    const int xx = x0 + (k % 5) - 2;
                    const bool valid = ((unsigned)yy < (unsigned)IMG_H) &&
                                       ((unsigned)xx < (unsigned)IMG_W);
                    float r = valid ? __ldg(proj_range + yy * IMG_W + xx) : 0.0f;
                    if (r < 0.0f) r = CUDART_INF_F;
                    d = fabsf(r - ur) * INV_G_C[k];
                }
                const unsigned long long c =
                    ((unsigned long long)__float_as_uint(d) << 32) | (unsigned)k;
                if (c < best) { best = c; bi = k; }
            }
            nm |= (1u << bi);
        }
        mask = nm;
    }

    const unsigned long long packed =
        ((unsigned long long)(mask & ib) << 32) |
        (unsigned)(y0 * IMG_W + x0);
    g_sel[p] = packed;    // OOB winners contribute zero: dropped via &ib
}

// ---------------------------------------------------------------------------
// Kernel B: accumulation. 5 threads/point (one float4 chunk each).
// ---------------------------------------------------------------------------
__global__ __launch_bounds__(256)
void knn_gather(const float4* __restrict__ probs4,   // [H*W][5] float4 (=20 ch)
                float4*       __restrict__ out4,     // [P][5] float4
                int P)
{
    int t = blockIdx.x * blockDim.x + threadIdx.x;
    if (t >= P * 5) return;

    const int p = t / 5;
    const int c = t - p * 5;

    const unsigned long long sel = g_sel[p];
    unsigned m     = (unsigned)(sel >> 32);
    const int base = (int)(sel & 0xFFFFFFFFu);   // y0*W + x0

    float4 acc = make_float4(0.f, 0.f, 0.f, 0.f);
    while (m) {
        const int k  = __ffs(m) - 1;
        m &= m - 1;
        const int ky = (k * 205) >> 10;          // k / 5
        const int kx = k - ky * 5;
        const int idx = base + (ky - 2) * IMG_W + (kx - 2);
        const float4 v = __ldg(probs4 + (size_t)idx * 5 + c);
        acc.x += v.x; acc.y += v.y; acc.z += v.z; acc.w += v.w;
    }

    out4[t] = acc;   // fully coalesced
}

extern "C" void kernel_launch(void* const* d_in, const int* in_sizes, int n_in,
                              void* d_out, int out_size)
{
    const float*  proj_range = (const float*)  d_in[0];
    const float*  unproj     = (const float*)  d_in[1];
    const float4* probs4     = (const float4*) d_in[2];
    const int*    px         = (const int*)    d_in[3];
    const int*    py         = (const int*)    d_in[4];
    float4*       out4       = (float4*)       d_out;

    int P = in_sizes[1];                 // unproj_range element count
    if (P > P_CAP) P = P_CAP;            // scratch capacity guard (fixed-shape problem)

    {
        const int threads = 256;
        const int blocks = (P + threads - 1) / threads;
        knn_select<<<blocks, threads>>>(proj_range, unproj, px, py, P);
    }
    {
        const int threads = 256;
        const int total = P * 5;
        const int blocks = (total + threads - 1) / threads;
        knn_gather<<<blocks, threads>>>(probs4, out4, P);
    }
}

// round 8
// speedup vs baseline: 1.2513x; 1.2513x over previous
#include <cuda_runtime.h>
#include <math_constants.h>

#define IMG_H 64
#define IMG_W 2048
#define KNN_CUTOFF 1.0f
#define P_CAP 131072
#define OVF_CAP 16384

// inv_g[k] = 1 - gauss(k)/sum(gauss), sigma=1, 5x5, row-major (ky,kx)
__device__ __constant__ float INV_G_C[25] = {
    0.99703098f, 0.98669378f, 0.97806177f, 0.98669378f, 0.99703098f,
    0.98669378f, 0.94036569f, 0.90167956f, 0.94036569f, 0.98669378f,
    0.97806177f, 0.90167956f, 0.83789717f, 0.90167956f, 0.97806177f,
    0.98669378f, 0.94036569f, 0.90167956f, 0.94036569f, 0.98669378f,
    0.99703098f, 0.98669378f, 0.97806177f, 0.98669378f, 0.99703098f
};

__device__ __forceinline__ constexpr float inv_g_k(int k) {
    constexpr float g[25] = {
        0.99703098f, 0.98669378f, 0.97806177f, 0.98669378f, 0.99703098f,
        0.98669378f, 0.94036569f, 0.90167956f, 0.94036569f, 0.98669378f,
        0.97806177f, 0.90167956f, 0.83789717f, 0.90167956f, 0.97806177f,
        0.98669378f, 0.94036569f, 0.90167956f, 0.94036569f, 0.98669378f,
        0.99703098f, 0.98669378f, 0.97806177f, 0.98669378f, 0.99703098f
    };
    return g[k];
}

// per point: (contribution mask << 32) | (y0*W + x0)
__device__ unsigned long long g_sel[P_CAP];
__device__ int g_ovf_count;
__device__ int g_ovf[OVF_CAP];

// ---------------------------------------------------------------------------
// Kernel A: cutoff-mask selection, FAST PATH ONLY. 1 thread/point.
// popc > 5 (~5e-4 of points) is deferred to knn_fixup via an overflow list.
// ---------------------------------------------------------------------------
__global__ __launch_bounds__(256)
void knn_select(const float* __restrict__ proj_range,
                const float* __restrict__ unproj,
                const int*   __restrict__ px,
                const int*   __restrict__ py,
                int P)
{
    int p = blockIdx.x * blockDim.x + threadIdx.x;
    if (p >= P) return;

    const int x0 = px[p];
    const int y0 = py[p];
    const float ur = unproj[p];

    unsigned maskAll = 0;   // cutoff passers incl. zero-padded OOB (for >5 trigger)
    unsigned maskIB  = 0;   // cutoff passers that are in-bounds (contributors)

    if (x0 >= 2 && x0 <= IMG_W - 3) {
        // interior columns (~99.75%): 2 aligned float4 loads per row
        const int xb   = x0 - 2;
        const int base = xb & ~3;          // aligned, in [0, W-8] since W%4==0
        const bool b1  = (xb & 2) != 0;
        const bool b0  = (xb & 1) != 0;
#pragma unroll
        for (int row = 0; row < 5; ++row) {
            const int yy  = y0 + row - 2;
            const bool rv = ((unsigned)yy < (unsigned)IMG_H);
            const int yyc = rv ? yy : 0;
            const float4* rp = (const float4*)(proj_range + yyc * IMG_W + base);
            const float4 lo = __ldg(rp);
            const float4 hi = __ldg(rp + 1);
            // select window f[xb&3 .. xb&3+4] out of 8 via 2-level tree
            const float h0 = b1 ? lo.z : lo.x;
            const float h1 = b1 ? lo.w : lo.y;
            const float h2 = b1 ? hi.x : lo.z;
            const float h3 = b1 ? hi.y : lo.w;
            const float h4 = b1 ? hi.z : hi.x;
            const float h5 = b1 ? hi.w : hi.y;
            float wv[5];
            wv[0] = b0 ? h1 : h0;
            wv[1] = b0 ? h2 : h1;
            wv[2] = b0 ? h3 : h2;
            wv[3] = b0 ? h4 : h3;
            wv[4] = b0 ? h5 : h4;
#pragma unroll
            for (int i = 0; i < 5; ++i) {
                const int k = row * 5 + i;
                const float r = rv ? wv[i] : 0.0f;   // OOB row padded 0 like unfold
                const float d = fabsf(r - ur) * inv_g_k(k);
                const bool pass = (d <= KNN_CUTOFF) && (r >= 0.0f);
                if (pass)       maskAll |= (1u << k);
                if (pass && rv) maskIB  |= (1u << k);
            }
        }
    } else {
        // edge columns (~0.25%): scalar clamped loads
#pragma unroll
        for (int k = 0; k < 25; ++k) {
            const int yy = y0 + (k / 5) - 2;
            const int xx = x0 + (k % 5) - 2;
            const bool valid = ((unsigned)yy < (unsigned)IMG_H) &&
                               ((unsigned)xx < (unsigned)IMG_W);
            const int yyc = valid ? yy : 0;
            const int xxc = valid ? xx : 0;
            const float rr = __ldg(proj_range + yyc * IMG_W + xxc);
            const float r  = valid ? rr : 0.0f;
            const float d  = fabsf(r - ur) * inv_g_k(k);
            const bool pass = (d <= KNN_CUTOFF) && (r >= 0.0f);
            if (pass)          maskAll |= (1u << k);
            if (pass && valid) maskIB  |= (1u << k);
        }
    }

    maskAll |= (1u << 12);   // center: d forced to 0, always passes, in-bounds
    maskIB  |= (1u << 12);

    if (__popc(maskAll) > 5) {
        const int slot = atomicAdd(&g_ovf_count, 1);
        if (slot < OVF_CAP) g_ovf[slot] = p;     // fixup overwrites g_sel[p]
    }

    g_sel[p] = ((unsigned long long)maskIB << 32) |
               (unsigned)(y0 * IMG_W + x0);
}

// ---------------------------------------------------------------------------
// Kernel F: exact top-5 for overflow points (register min-trees, R3-proven).
// ---------------------------------------------------------------------------
__global__ __launch_bounds__(128)
void knn_fixup(const float* __restrict__ proj_range,
               const float* __restrict__ unproj,
               const int*   __restrict__ px,
               const int*   __restrict__ py)
{
    int n = g_ovf_count;
    if (n > OVF_CAP) n = OVF_CAP;
    for (int i = blockIdx.x * blockDim.x + threadIdx.x; i < n;
         i += gridDim.x * blockDim.x) {
        const int p  = g_ovf[i];
        const int x0 = px[p];
        const int y0 = py[p];
        const float ur = unproj[p];

        unsigned key[25];
        unsigned ib = 0;
#pragma unroll
        for (int k = 0; k < 25; ++k) {
            const int yy = y0 + (k / 5) - 2;
            const int xx = x0 + (k % 5) - 2;
            const bool valid = ((unsigned)yy < (unsigned)IMG_H) &&
                               ((unsigned)xx < (unsigned)IMG_W);
            const int yyc = valid ? yy : 0;
            const int xxc = valid ? xx : 0;
            float r = valid ? __ldg(proj_range + yyc * IMG_W + xxc) : 0.0f;
            if (r < 0.0f) r = CUDART_INF_F;
            if (k == 12)  r = ur;
            key[k] = __float_as_uint(fabsf(r - ur) * INV_G_C[k]);
            if (valid) ib |= (1u << k);
        }

        unsigned nm = 0;
#pragma unroll
        for (int sel = 0; sel < 5; ++sel) {
            unsigned v[32];
#pragma unroll
            for (int k = 0; k < 25; ++k) v[k] = key[k];
#pragma unroll
            for (int k = 25; k < 32; ++k) v[k] = 0xFFFFFFFFu;
#pragma unroll
            for (int s = 16; s >= 1; s >>= 1)
#pragma unroll
                for (int j = 0; j < s; ++j) v[j] = min(v[j], v[j + s]);
            const unsigned m = v[0];

            unsigned ix[32];
#pragma unroll
            for (int k = 0; k < 25; ++k) ix[k] = (key[k] == m) ? (unsigned)k : 32u;
#pragma unroll
            for (int k = 25; k < 32; ++k) ix[k] = 32u;
#pragma unroll
            for (int s = 16; s >= 1; s >>= 1)
#pragma unroll
                for (int j = 0; j < s; ++j) ix[j] = min(ix[j], ix[j + s]);
            const unsigned bi = ix[0];

            // winners here all have d <= cutoff (>5 passers existed)
            nm |= (1u << bi);
#pragma unroll
            for (int k = 0; k < 25; ++k)
                if ((unsigned)k == bi) key[k] = 0xFFFFFFFFu;
        }

        g_sel[p] = ((unsigned long long)(nm & ib) << 32) |
                   (unsigned)(y0 * IMG_W + x0);
    }
}

// ---------------------------------------------------------------------------
// Kernel B: accumulation. 5 threads/point. Mask has <=5 bits: pre-extract
// all indices, issue all gathers predicated (MLP 5), then accumulate.
// ---------------------------------------------------------------------------
__global__ __launch_bounds__(256)
void knn_gather(const float4* __restrict__ probs4,   // [H*W][5] float4 (=20 ch)
                float4*       __restrict__ out4,     // [P][5] float4
                int P)
{
    int t = blockIdx.x * blockDim.x + threadIdx.x;
    if (t >= P * 5) return;

    const int p = t / 5;
    const int c = t - p * 5;

    const unsigned long long sel = g_sel[p];
    const unsigned m  = (unsigned)(sel >> 32);
    const int base    = (int)(sel & 0xFFFFFFFFu);   // y0*W + x0

    // pre-extract up to 5 set-bit positions (short serial FLO chain)
    int kk[5];
    {
        unsigned mm = m;
#pragma unroll
        for (int i = 0; i < 5; ++i) {
            kk[i] = __ffs(mm) - 1;      // -1 when exhausted
            mm &= mm - 1;
        }
    }

    // issue all gathers predicated; off = k + 2043*ky - 4098
    float4 v[5];
#pragma unroll
    for (int i = 0; i < 5; ++i) {
        const int k  = kk[i];
        const int ky = (k * 205) >> 10;             // k/5 for k in [0,24]
        const int idx = base + k + ky * 2043 - 4098;
        if (k >= 0) v[i] = __ldg(probs4 + (size_t)idx * 5 + c);
    }

    float4 acc = make_float4(0.f, 0.f, 0.f, 0.f);
#pragma unroll
    for (int i = 0; i < 5; ++i) {
        if (kk[i] >= 0) {
            acc.x += v[i].x; acc.y += v[i].y;
            acc.z += v[i].z; acc.w += v[i].w;
        }
    }

    out4[t] = acc;   // fully coalesced
}

extern "C" void kernel_launch(void* const* d_in, const int* in_sizes, int n_in,
                              void* d_out, int out_size)
{
    const float*  proj_range = (const float*)  d_in[0];
    const float*  unproj     = (const float*)  d_in[1];
    const float4* probs4     = (const float4*) d_in[2];
    const int*    px         = (const int*)    d_in[3];
    const int*    py         = (const int*)    d_in[4];
    float4*       out4       = (float4*)       d_out;

    int P = in_sizes[1];                 // unproj_range element count
    if (P > P_CAP) P = P_CAP;            // scratch capacity guard (fixed-shape problem)

    void* cnt_ptr = nullptr;
    cudaGetSymbolAddress(&cnt_ptr, g_ovf_count);
    cudaMemsetAsync(cnt_ptr, 0, sizeof(int));

    {
        const int threads = 256;
        const int blocks = (P + threads - 1) / threads;
        knn_select<<<blocks, threads>>>(proj_range, unproj, px, py, P);
    }
    knn_fixup<<<2, 128>>>(proj_range, unproj, px, py);
    {
        const int threads = 256;
        const int total = P * 5;
        const int blocks = (total + threads - 1) / threads;
        knn_gather<<<blocks, threads>>>(probs4, out4, P);
    }
}